// round 5
// baseline (speedup 1.0000x reference)
#include <cuda_runtime.h>
#include <cuda_bf16.h>
#include <cstdint>

#define N_NODES 50000
#define N_EDGES 600000
#define DIM     128
#define LN_EPS  1e-5f

// ---------------------------------------------------------------------------
// Scratch (device globals: allocation-free per harness rules)
// ---------------------------------------------------------------------------
__device__ float g_agg[N_NODES * DIM];
__device__ int   g_degin_i[N_NODES];
__device__ int   g_degout_i[N_NODES];
__device__ float g_outnorm[N_NODES];
__device__ float g_innorm[N_NODES];
__device__ int   g_off[N_NODES + 1];
__device__ int   g_cursor[N_NODES];
__device__ int   g_ssrc[N_EDGES];
// B tiles (bf16, plain [n][k] layout): [h0_hi | h0_lo | h1_hi | h1_lo]
__device__ __align__(16) uint8_t g_Bt[4 * 32768];

// ---------------------------------------------------------------------------
// Histogram: in/out degree counts (int)
// ---------------------------------------------------------------------------
__global__ void hist_kernel(const int* __restrict__ src, const int* __restrict__ dst) {
    int e = blockIdx.x * blockDim.x + threadIdx.x;
    if (e < N_EDGES) {
        atomicAdd(&g_degout_i[src[e]], 1);
        atomicAdd(&g_degin_i[dst[e]], 1);
    }
}

__global__ void norm_kernel() {
    int i = blockIdx.x * blockDim.x + threadIdx.x;
    if (i < N_NODES) {
        g_outnorm[i] = rsqrtf(fmaxf((float)g_degout_i[i], 1.0f));
        g_innorm[i]  = rsqrtf(fmaxf((float)g_degin_i[i], 1.0f));
    }
}

// ---------------------------------------------------------------------------
// Exclusive prefix scan of degin (one block, 1024 threads, chunk=49)
// Writes g_off[0..N_NODES] and g_cursor copy.
// ---------------------------------------------------------------------------
__global__ __launch_bounds__(1024) void scan_kernel() {
    __shared__ int part[1024];
    const int t = threadIdx.x;
    const int CH = (N_NODES + 1023) / 1024;   // 49
    const int beg = t * CH;
    int s = 0;
#pragma unroll 4
    for (int i = 0; i < CH; i++) {
        int idx = beg + i;
        if (idx < N_NODES) s += g_degin_i[idx];
    }
    part[t] = s;
    __syncthreads();
    for (int off = 1; off < 1024; off <<= 1) {
        int v = (t >= off) ? part[t - off] : 0;
        __syncthreads();
        if (t >= off) part[t] += v;
        __syncthreads();
    }
    int run = (t == 0) ? 0 : part[t - 1];
    for (int i = 0; i < CH; i++) {
        int idx = beg + i;
        if (idx < N_NODES) {
            g_off[idx] = run;
            g_cursor[idx] = run;
            run += g_degin_i[idx];
        }
    }
    if (t == 1023) g_off[N_NODES] = run;
}

// ---------------------------------------------------------------------------
// Scatter edges into dst-sorted order (bucket order nondeterministic; sums
// use fp32 so rounding varies negligibly — same as atomic baseline).
// ---------------------------------------------------------------------------
__global__ void scatter_kernel(const int* __restrict__ src, const int* __restrict__ dst) {
    int e = blockIdx.x * blockDim.x + threadIdx.x;
    if (e < N_EDGES) {
        int pos = atomicAdd(&g_cursor[dst[e]], 1);
        g_ssrc[pos] = src[e];
    }
}

// ---------------------------------------------------------------------------
// CSR aggregation: one warp per node, full row accumulated in registers.
// agg[n] = sum_{e in bucket(n)} feat[src_e] * outnorm[src_e]
// ---------------------------------------------------------------------------
__global__ __launch_bounds__(256) void agg_kernel(const float* __restrict__ feat) {
    const int warp = (blockIdx.x * blockDim.x + threadIdx.x) >> 5;
    const int lane = threadIdx.x & 31;
    if (warp >= N_NODES) return;
    const int beg = g_off[warp];
    const int end = g_off[warp + 1];
    float4 acc = make_float4(0.f, 0.f, 0.f, 0.f);
    const float4* feat4 = reinterpret_cast<const float4*>(feat);
    for (int base = beg; base < end; base += 32) {
        int m = end - base; if (m > 32) m = 32;
        int  s_l  = 0;
        float on_l = 0.f;
        if (base + lane < end) {
            s_l = g_ssrc[base + lane];
            on_l = g_outnorm[s_l];
        }
        for (int j = 0; j < m; j++) {
            int   s  = __shfl_sync(0xFFFFFFFFu, s_l, j);
            float on = __shfl_sync(0xFFFFFFFFu, on_l, j);
            float4 v = feat4[(size_t)s * 32 + lane];
            acc.x = fmaf(v.x, on, acc.x);
            acc.y = fmaf(v.y, on, acc.y);
            acc.z = fmaf(v.z, on, acc.z);
            acc.w = fmaf(v.w, on, acc.w);
        }
    }
    reinterpret_cast<float4*>(g_agg)[(size_t)warp * 32 + lane] = acc;
}

// ---------------------------------------------------------------------------
// bf16 hi/lo split
// ---------------------------------------------------------------------------
__device__ __forceinline__ void split_bf16(float x, uint16_t& hi, uint16_t& lo) {
    __nv_bfloat16 h = __float2bfloat16(x);
    hi = __bfloat16_as_ushort(h);
    float hf = __uint_as_float((uint32_t)hi << 16);
    lo = __bfloat16_as_ushort(__float2bfloat16(x - hf));
}

// ---------------------------------------------------------------------------
// Prep: W[k][n] (fc_w half0, res_w half1) -> Bt[n][k] bf16 hi/lo tiles
// ---------------------------------------------------------------------------
__global__ void prep_b_kernel(const float* __restrict__ fc_w,
                              const float* __restrict__ res_w) {
    int id = blockIdx.x * blockDim.x + threadIdx.x;   // 0..4095
    int h  = id >> 11;
    int rem = id & 2047;
    int n  = rem >> 4;
    int kb = (rem & 15) * 8;
    const float* W = h ? res_w : fc_w;
    uint32_t hp[4], lp[4];
#pragma unroll
    for (int j = 0; j < 4; j++) {
        uint16_t h0, l0, h1, l1;
        split_bf16(W[(kb + 2 * j)     * DIM + n], h0, l0);
        split_bf16(W[(kb + 2 * j + 1) * DIM + n], h1, l1);
        hp[j] = ((uint32_t)h1 << 16) | h0;
        lp[j] = ((uint32_t)l1 << 16) | l0;
    }
    uint32_t off = (uint32_t)(n * 256 + kb * 2);
    *reinterpret_cast<uint4*>(&g_Bt[(uint32_t)(h * 2)     * 32768u + off]) =
        make_uint4(hp[0], hp[1], hp[2], hp[3]);
    *reinterpret_cast<uint4*>(&g_Bt[(uint32_t)(h * 2 + 1) * 32768u + off]) =
        make_uint4(lp[0], lp[1], lp[2], lp[3]);
}

// ---------------------------------------------------------------------------
// mma.sync bf16 GEMM + bias + LayerNorm + ReLU (3-term split, fp32 accum)
// ---------------------------------------------------------------------------
#define ROW_BYTES 272
#define TILE_BYTES (128 * ROW_BYTES)
#define SMEM_B     0
#define SMEM_A_HI  (4 * TILE_BYTES)
#define SMEM_A_LO  (SMEM_A_HI + TILE_BYTES)
#define SMEM_STATS (SMEM_A_LO + TILE_BYTES)
#define SMEM_TOTAL (SMEM_STATS + 2048)

__device__ __forceinline__ uint32_t smem_u32(const void* p) {
    uint32_t a;
    asm("{ .reg .u64 t; cvta.to.shared.u64 t, %1; cvt.u32.u64 %0, t; }"
        : "=r"(a) : "l"(p));
    return a;
}
__device__ __forceinline__ void ldsm4(uint32_t (&r)[4], uint32_t addr) {
    asm volatile("ldmatrix.sync.aligned.m8n8.x4.shared.b16 {%0,%1,%2,%3}, [%4];"
                 : "=r"(r[0]), "=r"(r[1]), "=r"(r[2]), "=r"(r[3]) : "r"(addr));
}
__device__ __forceinline__ void mma16816(float (&d)[4], const uint32_t (&a)[4],
                                         uint32_t b0, uint32_t b1) {
    asm volatile("mma.sync.aligned.m16n8k16.row.col.f32.bf16.bf16.f32 "
                 "{%0,%1,%2,%3}, {%4,%5,%6,%7}, {%8,%9}, {%0,%1,%2,%3};"
                 : "+f"(d[0]), "+f"(d[1]), "+f"(d[2]), "+f"(d[3])
                 : "r"(a[0]), "r"(a[1]), "r"(a[2]), "r"(a[3]), "r"(b0), "r"(b1));
}

__global__ __launch_bounds__(256) void gemm_mma_kernel(
    const float* __restrict__ feat,
    const float* __restrict__ fc_b,
    const float* __restrict__ ln_g,
    const float* __restrict__ ln_b,
    float* __restrict__ out)
{
    extern __shared__ __align__(16) char smem[];
    const uint32_t sb = smem_u32(smem);
    const int tid  = threadIdx.x;
    const int wid  = tid >> 5;
    const int lane = tid & 31;
    const int wm   = wid & 3;
    const int wn   = wid >> 2;
    const int bm0  = blockIdx.x * 128;

    // ---- copy B tiles into padded SMEM layout ----
    {
        const uint4* src = reinterpret_cast<const uint4*>(g_Bt);
#pragma unroll
        for (int i = 0; i < 32; i++) {
            int idx = tid + i * 256;
            int t = idx >> 11, rem = idx & 2047;
            int n = rem >> 4, c = rem & 15;
            uint4 v = src[t * 2048 + n * 16 + c];
            *reinterpret_cast<uint4*>(smem + SMEM_B + t * TILE_BYTES + n * ROW_BYTES + c * 16) = v;
        }
    }

    auto load_a_half = [&](int half) {
        const float* Ap = half ? feat : g_agg;
        const int r0 = tid >> 4;
        const int kb = (tid & 15) * 8;
#pragma unroll
        for (int pass = 0; pass < 8; pass++) {
            int row_l = pass * 16 + r0;
            int row_g = bm0 + row_l;
            float x[8];
            if (row_g < N_NODES) {
                float4 v0 = *reinterpret_cast<const float4*>(Ap + (size_t)row_g * DIM + kb);
                float4 v1 = *reinterpret_cast<const float4*>(Ap + (size_t)row_g * DIM + kb + 4);
                x[0]=v0.x; x[1]=v0.y; x[2]=v0.z; x[3]=v0.w;
                x[4]=v1.x; x[5]=v1.y; x[6]=v1.z; x[7]=v1.w;
                if (half == 0) {
                    float s = g_innorm[row_g];
#pragma unroll
                    for (int j = 0; j < 8; j++) x[j] *= s;
                }
            } else {
#pragma unroll
                for (int j = 0; j < 8; j++) x[j] = 0.0f;
            }
            uint32_t hp[4], lp[4];
#pragma unroll
            for (int j = 0; j < 4; j++) {
                uint16_t h0, l0, h1, l1;
                split_bf16(x[2 * j], h0, l0);
                split_bf16(x[2 * j + 1], h1, l1);
                hp[j] = ((uint32_t)h1 << 16) | h0;
                lp[j] = ((uint32_t)l1 << 16) | l0;
            }
            uint32_t off = (uint32_t)(row_l * ROW_BYTES + kb * 2);
            *reinterpret_cast<uint4*>(smem + SMEM_A_HI + off) = make_uint4(hp[0], hp[1], hp[2], hp[3]);
            *reinterpret_cast<uint4*>(smem + SMEM_A_LO + off) = make_uint4(lp[0], lp[1], lp[2], lp[3]);
        }
    };

    float acc[2][8][4];
#pragma unroll
    for (int m = 0; m < 2; m++)
#pragma unroll
        for (int n = 0; n < 8; n++)
#pragma unroll
            for (int c = 0; c < 4; c++) acc[m][n][c] = 0.0f;

    const uint32_t lane_off = (uint32_t)((lane & 15) * ROW_BYTES + (lane >> 4) * 16);

    auto compute_half = [&](int half) {
        const uint32_t bhi = sb + SMEM_B + (uint32_t)(half * 2) * TILE_BYTES;
        const uint32_t blo = bhi + TILE_BYTES;
        const uint32_t ahi = sb + SMEM_A_HI + (uint32_t)(wm * 32) * ROW_BYTES;
        const uint32_t alo = sb + SMEM_A_LO + (uint32_t)(wm * 32) * ROW_BYTES;
#pragma unroll 2
        for (int ks = 0; ks < 8; ks++) {
            const uint32_t koff = (uint32_t)(ks * 32) + lane_off;
            uint32_t ah[2][4], al[2][4];
            ldsm4(ah[0], ahi + koff);
            ldsm4(ah[1], ahi + 16 * ROW_BYTES + koff);
            ldsm4(al[0], alo + koff);
            ldsm4(al[1], alo + 16 * ROW_BYTES + koff);
#pragma unroll
            for (int ng = 0; ng < 4; ng++) {
                uint32_t bh[4], bl[4];
                const uint32_t nrow = (uint32_t)((wn * 64 + ng * 16) * ROW_BYTES);
                ldsm4(bh, bhi + nrow + koff);
                ldsm4(bl, blo + nrow + koff);
#pragma unroll
                for (int m = 0; m < 2; m++) {
                    mma16816(acc[m][2 * ng],     ah[m], bh[0], bh[2]);
                    mma16816(acc[m][2 * ng + 1], ah[m], bh[1], bh[3]);
                    mma16816(acc[m][2 * ng],     ah[m], bl[0], bl[2]);
                    mma16816(acc[m][2 * ng + 1], ah[m], bl[1], bl[3]);
                    mma16816(acc[m][2 * ng],     al[m], bh[0], bh[2]);
                    mma16816(acc[m][2 * ng + 1], al[m], bh[1], bh[3]);
                }
            }
        }
    };

    load_a_half(0);
    __syncthreads();
    compute_half(0);
    __syncthreads();
    load_a_half(1);
    __syncthreads();
    compute_half(1);

    // ---- epilogue: bias*in_norm, LN stats, ReLU ----
    const int r = lane >> 2, q = lane & 3;
    int rowl[4];
    float innm[4];
#pragma unroll
    for (int mf = 0; mf < 2; mf++)
#pragma unroll
        for (int s = 0; s < 2; s++) {
            int i = mf * 2 + s;
            rowl[i] = wm * 32 + mf * 16 + s * 8 + r;
            int row_g = bm0 + rowl[i];
            innm[i] = (row_g < N_NODES) ? g_innorm[row_g] : 0.0f;
        }

    float s1[4] = {0.f, 0.f, 0.f, 0.f}, s2[4] = {0.f, 0.f, 0.f, 0.f};
#pragma unroll
    for (int nf = 0; nf < 8; nf++) {
        int col = wn * 64 + nf * 8 + q * 2;
        float2 bs = *reinterpret_cast<const float2*>(fc_b + col);
#pragma unroll
        for (int mf = 0; mf < 2; mf++)
#pragma unroll
            for (int s = 0; s < 2; s++) {
                int i = mf * 2 + s;
                float x = acc[mf][nf][s * 2]     + innm[i] * bs.x;
                float y = acc[mf][nf][s * 2 + 1] + innm[i] * bs.y;
                acc[mf][nf][s * 2] = x;
                acc[mf][nf][s * 2 + 1] = y;
                s1[i] += x + y;
                s2[i] += x * x + y * y;
            }
    }
#pragma unroll
    for (int o = 1; o <= 2; o <<= 1)
#pragma unroll
        for (int i = 0; i < 4; i++) {
            s1[i] += __shfl_xor_sync(0xFFFFFFFFu, s1[i], o);
            s2[i] += __shfl_xor_sync(0xFFFFFFFFu, s2[i], o);
        }

    float2* stats = reinterpret_cast<float2*>(smem + SMEM_STATS);
    if (q == 0) {
#pragma unroll
        for (int i = 0; i < 4; i++)
            stats[rowl[i] * 2 + wn] = make_float2(s1[i], s2[i]);
    }
    __syncthreads();

    float mu[4], inv[4];
#pragma unroll
    for (int i = 0; i < 4; i++) {
        float2 a0 = stats[rowl[i] * 2];
        float2 a1 = stats[rowl[i] * 2 + 1];
        float S = a0.x + a1.x, S2 = a0.y + a1.y;
        mu[i] = S * (1.0f / DIM);
        float var = S2 * (1.0f / DIM) - mu[i] * mu[i];
        inv[i] = rsqrtf(var + LN_EPS);
    }

#pragma unroll
    for (int nf = 0; nf < 8; nf++) {
        int col = wn * 64 + nf * 8 + q * 2;
        float2 g2 = *reinterpret_cast<const float2*>(ln_g + col);
        float2 b2 = *reinterpret_cast<const float2*>(ln_b + col);
#pragma unroll
        for (int mf = 0; mf < 2; mf++)
#pragma unroll
            for (int s = 0; s < 2; s++) {
                int i = mf * 2 + s;
                int row_g = bm0 + rowl[i];
                if (row_g < N_NODES) {
                    float2 o;
                    o.x = fmaxf((acc[mf][nf][s * 2]     - mu[i]) * inv[i] * g2.x + b2.x, 0.f);
                    o.y = fmaxf((acc[mf][nf][s * 2 + 1] - mu[i]) * inv[i] * g2.y + b2.y, 0.f);
                    *reinterpret_cast<float2*>(out + (size_t)row_g * DIM + col) = o;
                }
            }
    }
}

// ---------------------------------------------------------------------------
extern "C" void kernel_launch(void* const* d_in, const int* in_sizes, int n_in,
                              void* d_out, int out_size) {
    const float* feat  = (const float*)d_in[0];
    const int*   src   = (const int*)d_in[1];
    const int*   dst   = (const int*)d_in[2];
    const float* fc_w  = (const float*)d_in[3];
    const float* fc_b  = (const float*)d_in[4];
    const float* res_w = (const float*)d_in[5];
    const float* ln_g  = (const float*)d_in[6];
    const float* ln_b  = (const float*)d_in[7];
    float* out = (float*)d_out;

    void *din_p, *dout_p;
    cudaGetSymbolAddress(&din_p, g_degin_i);
    cudaGetSymbolAddress(&dout_p, g_degout_i);
    cudaMemsetAsync(din_p, 0, sizeof(int) * N_NODES);
    cudaMemsetAsync(dout_p, 0, sizeof(int) * N_NODES);

    hist_kernel<<<(N_EDGES + 255) / 256, 256>>>(src, dst);
    scan_kernel<<<1, 1024>>>();
    norm_kernel<<<(N_NODES + 255) / 256, 256>>>();
    scatter_kernel<<<(N_EDGES + 255) / 256, 256>>>(src, dst);
    prep_b_kernel<<<16, 256>>>(fc_w, res_w);
    agg_kernel<<<(N_NODES * 32 + 255) / 256, 256>>>(feat);

    cudaFuncSetAttribute(gemm_mma_kernel,
                         cudaFuncAttributeMaxDynamicSharedMemorySize, SMEM_TOTAL);
    gemm_mma_kernel<<<(N_NODES + 127) / 128, 256, SMEM_TOTAL>>>(feat, fc_b, ln_g, ln_b, out);
}